// round 15
// baseline (speedup 1.0000x reference)
#include <cuda_runtime.h>
#include <cuda_bf16.h>
#include <cstdint>

typedef unsigned long long ull;

#define B_SZ  16384
#define V_DIM 20
#define F_DIM 15

// ---------------------------------------------------------------------------
// f32x2 packed math helpers (fp32 GRU path)
// ---------------------------------------------------------------------------
__device__ __forceinline__ ull pk2(float a) {
    ull r; asm("mov.b64 %0, {%1, %1};" : "=l"(r) : "f"(a)); return r;
}
__device__ __forceinline__ void ffma2(ull &d, ull a, ull b) {
    asm("fma.rn.f32x2 %0, %1, %2, %0;" : "+l"(d) : "l"(a), "l"(b));
}
__device__ __forceinline__ float2 upk(ull v) {
    float2 f; asm("mov.b64 {%0, %1}, %2;" : "=f"(f.x), "=f"(f.y) : "l"(v)); return f;
}
__device__ __forceinline__ float tanhfast(float x) {
    float y; asm("tanh.approx.f32 %0, %1;" : "=f"(y) : "f"(x)); return y;
}
__device__ __forceinline__ float sigmfast(float x) {
    return fmaf(tanhfast(0.5f * x), 0.5f, 0.5f);
}

// ---------------------------------------------------------------------------
// mma.sync + cp.async helpers (sm_80+ PTX: legal on compute_103)
// ---------------------------------------------------------------------------
__device__ __forceinline__ uint32_t smem_u32(const void* p) {
    uint32_t a;
    asm("{ .reg .u64 t; cvta.to.shared.u64 t, %1; cvt.u32.u64 %0, t; }"
        : "=r"(a) : "l"(p));
    return a;
}
__device__ __forceinline__ void ldm4(uint32_t* r, uint32_t addr) {
    asm volatile("ldmatrix.sync.aligned.m8n8.x4.shared.b16 {%0,%1,%2,%3}, [%4];"
                 : "=r"(r[0]), "=r"(r[1]), "=r"(r[2]), "=r"(r[3]) : "r"(addr));
}
__device__ __forceinline__ void mma16816(float* c, const uint32_t* a,
                                         uint32_t b0, uint32_t b1) {
    asm volatile(
        "mma.sync.aligned.m16n8k16.row.col.f32.bf16.bf16.f32 "
        "{%0,%1,%2,%3}, {%4,%5,%6,%7}, {%8,%9}, {%0,%1,%2,%3};"
        : "+f"(c[0]), "+f"(c[1]), "+f"(c[2]), "+f"(c[3])
        : "r"(a[0]), "r"(a[1]), "r"(a[2]), "r"(a[3]), "r"(b0), "r"(b1));
}
__device__ __forceinline__ void cpa16(uint32_t dst, const void* src) {
    asm volatile("cp.async.cg.shared.global [%0], [%1], 16;"
                 :: "r"(dst), "l"(src));
}
#define CPA_COMMIT() asm volatile("cp.async.commit_group;" ::: "memory")
#define CPA_WAIT(n)  asm volatile("cp.async.wait_group %0;" :: "n"(n) : "memory")

// ---------------------------------------------------------------------------
// Device-global scratch
// ---------------------------------------------------------------------------
__device__ float g_WhhT[256 * 768];
__device__ float g_WihT[16 * 768];
__device__ float g_state16[(size_t)B_SZ * V_DIM * 16];
__device__ float g_xg[(size_t)B_SZ * V_DIM * 768];
__device__ float g_out4[(size_t)B_SZ * 256];

// bf16 split buffers (16B-aligned for uint4 / cp.async access)
__device__ __align__(16) __nv_bfloat16 g_xh[(size_t)B_SZ * 320];
__device__ __align__(16) __nv_bfloat16 g_xl[(size_t)B_SZ * 320];
__device__ __align__(16) __nv_bfloat16 g_ah[(size_t)B_SZ * 1024];
__device__ __align__(16) __nv_bfloat16 g_al[(size_t)B_SZ * 1024];
__device__ __align__(16) __nv_bfloat16 g_bh[(size_t)B_SZ * 1024];
__device__ __align__(16) __nv_bfloat16 g_bl[(size_t)B_SZ * 1024];
__device__ __align__(16) __nv_bfloat16 g_w1h[1024 * 320];
__device__ __align__(16) __nv_bfloat16 g_w1l[1024 * 320];
__device__ __align__(16) __nv_bfloat16 g_w2h[1024 * 1024];
__device__ __align__(16) __nv_bfloat16 g_w2l[1024 * 1024];
__device__ __align__(16) __nv_bfloat16 g_w3h[512 * 1024];
__device__ __align__(16) __nv_bfloat16 g_w3l[512 * 1024];
__device__ __align__(16) __nv_bfloat16 g_w4h[256 * 512];
__device__ __align__(16) __nv_bfloat16 g_w4l[256 * 512];

// ---------------------------------------------------------------------------
// Prep kernels
// ---------------------------------------------------------------------------
__global__ void transpose_pad(const float* __restrict__ in, float* __restrict__ out,
                              int N, int K, int Kp)
{
    int idx = blockIdx.x * 256 + threadIdx.x;
    if (idx >= Kp * N) return;
    int k = idx / N, n = idx - k * N;
    out[idx] = (k < K) ? in[n * K + k] : 0.0f;
}

__global__ void pad_state16(const float* __restrict__ s, float* __restrict__ o)
{
    int idx = blockIdx.x * 256 + threadIdx.x;
    if (idx >= B_SZ * V_DIM * 16) return;
    int r = idx >> 4, c = idx & 15;
    o[idx] = (c < F_DIM) ? s[r * F_DIM + c] : 0.0f;
}

// generic bf16 hi/lo split with K padding: in [N][K] -> out [N][Kp]
__global__ void split_pad(const float* __restrict__ in,
                          __nv_bfloat16* __restrict__ hi, __nv_bfloat16* __restrict__ lo,
                          int N, int K, int Kp)
{
    int idx = blockIdx.x * 256 + threadIdx.x;
    if (idx >= N * Kp) return;
    int n = idx / Kp, k = idx - n * Kp;
    float v = (k < K) ? in[(size_t)n * K + k] : 0.0f;
    __nv_bfloat16 h = __float2bfloat16(v);
    hi[idx] = h;
    lo[idx] = __float2bfloat16(v - __bfloat162float(h));
}

// W1 split with column permutation matching xcat = [h(256)|feat(15)|pad]
__global__ void split_w1(const float* __restrict__ W1,
                         __nv_bfloat16* __restrict__ hi, __nv_bfloat16* __restrict__ lo)
{
    int idx = blockIdx.x * 256 + threadIdx.x;
    if (idx >= 1024 * 320) return;
    int n = idx / 320, k = idx - n * 320;
    float v = 0.0f;
    if (k < 256)      v = W1[n * 271 + 15 + k];
    else if (k < 271) v = W1[n * 271 + (k - 256)];
    __nv_bfloat16 h = __float2bfloat16(v);
    hi[idx] = h;
    lo[idx] = __float2bfloat16(v - __bfloat162float(h));
}

// ---------------------------------------------------------------------------
// GRU kernel v2: 512 threads, occ 2 (8 warps/SMSP resident -> feed FFMA2 pipe)
// CTA = 32 batch rows. Thread: 8 rows x 2 cols x 3 gates (acc = 24 ull).
// h transposed in SMEM [k][36-row-padded] -> broadcast A loads.
// W tiles [8][768] double-buffered (smem 89KB total -> occ 2).
// Epilogue writes bf16 hi/lo xcat directly (kills separate split kernel).
// ---------------------------------------------------------------------------
#define ASTRIDE 36
#define GRU_SMEM_FLOATS (2 * 8 * 768 + 256 * ASTRIDE + 768)
#define GRU_SMEM_BYTES  (GRU_SMEM_FLOATS * 4)

__global__ __launch_bounds__(512, 2)
void gru_kernel(const float* __restrict__ state, const float* __restrict__ b_hh)
{
    extern __shared__ __align__(16) float sm[];
    float* W_s = sm;                       // [2][8*768]
    float* A_s = sm + 2 * 8 * 768;         // [256][ASTRIDE] (h transposed)
    float* bb  = A_s + 256 * ASTRIDE;      // [768] = b_hh

    const int tid  = threadIdx.x;
    const int w    = tid >> 5, lane = tid & 31;
    const int rg   = w >> 2;                    // row group 0..3
    const int r0   = rg * 8;
    const int hcol = (w & 3) * 64 + lane * 2;   // 2 cols within 256
    const int b0   = blockIdx.x * 32;

    for (int i = tid; i < 256 * ASTRIDE; i += 512) A_s[i] = 0.0f;
    for (int i = tid; i < 768; i += 512) bb[i] = b_hh[i];

    // stage weight tile 0 (8x768 floats, 3 float4 per thread)
    #pragma unroll
    for (int j = 0; j < 3; ++j) {
        int f = (tid + j * 512) * 4;
        *(float4*)(W_s + f) = *(const float4*)(g_WhhT + f);
    }
    __syncthreads();

    ull acc[3][8];
    #pragma unroll
    for (int g = 0; g < 3; ++g)
        #pragma unroll
        for (int i = 0; i < 8; ++i) acc[g][i] = 0ull;

    int buf = 0, nxt = 1;
    for (int t = 0; t < V_DIM; ++t) {
        for (int kt = 0; kt < 32; ++kt) {
            // stage next tile (weights identical every step -> mod-32 ring)
            {
                const float* src = g_WhhT + nxt * (8 * 768);
                float* dst = W_s + (buf ^ 1) * 6144;
                #pragma unroll
                for (int j = 0; j < 3; ++j) {
                    int f = (tid + j * 512) * 4;
                    *(float4*)(dst + f) = *(const float4*)(src + f);
                }
            }
            // compute this tile (8 k's)
            const float* Wb = W_s + buf * 6144;
            #pragma unroll
            for (int kk = 0; kk < 8; ++kk) {
                const int k = kt * 8 + kk;
                float4 a0 = *(const float4*)(A_s + k * ASTRIDE + r0);
                float4 a1 = *(const float4*)(A_s + k * ASTRIDE + r0 + 4);
                ull pa[8];
                pa[0] = pk2(a0.x); pa[1] = pk2(a0.y); pa[2] = pk2(a0.z); pa[3] = pk2(a0.w);
                pa[4] = pk2(a1.x); pa[5] = pk2(a1.y); pa[6] = pk2(a1.z); pa[7] = pk2(a1.w);
                #pragma unroll
                for (int g = 0; g < 3; ++g) {
                    ull wv = *(const ull*)(Wb + kk * 768 + g * 256 + hcol);
                    #pragma unroll
                    for (int i = 0; i < 8; ++i) ffma2(acc[g][i], pa[i], wv);
                }
            }
            __syncthreads();
            buf ^= 1;
            nxt = (nxt + 1) & 31;
        }

        // ---- epilogue: gates + state update (thread-exclusive cells) ----
        float2 bR = *(const float2*)(bb + 0 * 256 + hcol);
        float2 bZ = *(const float2*)(bb + 1 * 256 + hcol);
        float2 bN = *(const float2*)(bb + 2 * 256 + hcol);
        #pragma unroll
        for (int i = 0; i < 8; ++i) {
            size_t xrow = ((size_t)(b0 + r0 + i) * V_DIM + t) * 768;
            float2 xr = *(const float2*)(g_xg + xrow + 0 * 256 + hcol);
            float2 xz = *(const float2*)(g_xg + xrow + 1 * 256 + hcol);
            float2 xn = *(const float2*)(g_xg + xrow + 2 * 256 + hcol);
            float2 ar = upk(acc[0][i]);
            float2 az = upk(acc[1][i]);
            float2 an = upk(acc[2][i]);
            float rr0 = sigmfast(xr.x + ar.x + bR.x);
            float rr1 = sigmfast(xr.y + ar.y + bR.y);
            float zz0 = sigmfast(xz.x + az.x + bZ.x);
            float zz1 = sigmfast(xz.y + az.y + bZ.y);
            float nn0 = tanhfast(xn.x + rr0 * (an.x + bN.x));
            float nn1 = tanhfast(xn.y + rr1 * (an.y + bN.y));
            float* hp0 = A_s + (hcol + 0) * ASTRIDE + r0 + i;
            float* hp1 = A_s + (hcol + 1) * ASTRIDE + r0 + i;
            float h0 = *hp0, h1 = *hp1;
            *hp0 = nn0 + zz0 * (h0 - nn0);
            *hp1 = nn1 + zz1 * (h1 - nn1);
        }
        #pragma unroll
        for (int g = 0; g < 3; ++g)
            #pragma unroll
            for (int i = 0; i < 8; ++i) acc[g][i] = 0ull;
        __syncthreads();
    }

    // ---- write xcat bf16 hi/lo directly: [h(256) | feat(15) | pad..320) ----
    #pragma unroll
    for (int i = 0; i < 8; ++i) {
        float v0 = A_s[(hcol + 0) * ASTRIDE + r0 + i];
        float v1 = A_s[(hcol + 1) * ASTRIDE + r0 + i];
        uint32_t hpk, lpk;
        asm("cvt.rn.bf16x2.f32 %0, %1, %2;" : "=r"(hpk) : "f"(v1), "f"(v0));
        float rv0 = v0 - __uint_as_float(hpk << 16);
        float rv1 = v1 - __uint_as_float(hpk & 0xffff0000u);
        asm("cvt.rn.bf16x2.f32 %0, %1, %2;" : "=r"(lpk) : "f"(rv1), "f"(rv0));
        size_t off = (size_t)(b0 + r0 + i) * 320 + hcol;
        *(uint32_t*)(g_xh + off) = hpk;
        *(uint32_t*)(g_xl + off) = lpk;
    }
    // features cols 256..270 (480 slots, 512 threads: single shot valid)
    if (tid < 32 * F_DIM) {
        int row = tid / F_DIM, f = tid - row * F_DIM;
        float v = state[((size_t)(b0 + row) * V_DIM) * F_DIM + f];
        __nv_bfloat16 h = __float2bfloat16(v);
        size_t off = (size_t)(b0 + row) * 320 + 256 + f;
        g_xh[off] = h;
        g_xl[off] = __float2bfloat16(v - __bfloat162float(h));
    }
    // zero pad cols 271..319
    for (int idx = tid; idx < 32 * 49; idx += 512) {
        int row = idx / 49, c = 271 + idx - (idx / 49) * 49;
        size_t off = (size_t)(b0 + row) * 320 + c;
        g_xh[off] = __float2bfloat16(0.0f);
        g_xl[off] = __float2bfloat16(0.0f);
    }
}

// ---------------------------------------------------------------------------
// fp32 GEMM (kept for the xg precompute: K=16, N=768)
// ---------------------------------------------------------------------------
__global__ __launch_bounds__(256, 2)
void mlp_gemm(const float* __restrict__ A, const float* __restrict__ Wt,
              const float* __restrict__ bias, float* __restrict__ C,
              int K, int N, int relu)
{
    __shared__ __align__(16) float A_s[2][16 * 128];
    __shared__ __align__(16) float W_s[2][16 * 128];

    const int tid  = threadIdx.x;
    const int tx   = tid & 15, ty = tid >> 4;
    const int m0   = blockIdx.y << 7, n0 = blockIdx.x << 7;
    const int crow = ty * 8;
    const int c1   = 4 * tx, c2 = 64 + 4 * tx;

    ull acc[8][4];
    #pragma unroll
    for (int j = 0; j < 8; ++j)
        #pragma unroll
        for (int c = 0; c < 4; ++c) acc[j][c] = 0ull;

    const int ar = tid >> 1;
    const int ac = (tid & 1) * 8;
    const int wk = ty;
    const int wc = 8 * tx;

    {
        const float* sa = A + (size_t)(m0 + ar) * K + ac;
        float4 a0 = *(const float4*)sa, a1 = *(const float4*)(sa + 4);
        A_s[0][(ac+0)*128+ar]=a0.x; A_s[0][(ac+1)*128+ar]=a0.y;
        A_s[0][(ac+2)*128+ar]=a0.z; A_s[0][(ac+3)*128+ar]=a0.w;
        A_s[0][(ac+4)*128+ar]=a1.x; A_s[0][(ac+5)*128+ar]=a1.y;
        A_s[0][(ac+6)*128+ar]=a1.z; A_s[0][(ac+7)*128+ar]=a1.w;
        const float* sw = Wt + (size_t)wk * N + n0 + wc;
        *(float4*)&W_s[0][wk*128+wc]   = *(const float4*)sw;
        *(float4*)&W_s[0][wk*128+wc+4] = *(const float4*)(sw + 4);
    }
    __syncthreads();

    const int ntile = K >> 4;
    for (int tk = 0; tk < ntile; ++tk) {
        const int cb = tk & 1;
        if (tk + 1 < ntile) {
            const int nb = cb ^ 1, k0 = (tk + 1) << 4;
            const float* sa = A + (size_t)(m0 + ar) * K + k0 + ac;
            float4 a0 = *(const float4*)sa, a1 = *(const float4*)(sa + 4);
            A_s[nb][(ac+0)*128+ar]=a0.x; A_s[nb][(ac+1)*128+ar]=a0.y;
            A_s[nb][(ac+2)*128+ar]=a0.z; A_s[nb][(ac+3)*128+ar]=a0.w;
            A_s[nb][(ac+4)*128+ar]=a1.x; A_s[nb][(ac+5)*128+ar]=a1.y;
            A_s[nb][(ac+6)*128+ar]=a1.z; A_s[nb][(ac+7)*128+ar]=a1.w;
            const float* sw = Wt + (size_t)(k0 + wk) * N + n0 + wc;
            *(float4*)&W_s[nb][wk*128+wc]   = *(const float4*)sw;
            *(float4*)&W_s[nb][wk*128+wc+4] = *(const float4*)(sw + 4);
        }
        #pragma unroll
        for (int k = 0; k < 16; ++k) {
            float4 a0 = *(const float4*)&A_s[cb][k * 128 + crow];
            float4 a1 = *(const float4*)&A_s[cb][k * 128 + crow + 4];
            ulonglong2 w1 = *(const ulonglong2*)&W_s[cb][k * 128 + c1];
            ulonglong2 w2 = *(const ulonglong2*)&W_s[cb][k * 128 + c2];
            float av[8] = {a0.x, a0.y, a0.z, a0.w, a1.x, a1.y, a1.z, a1.w};
            #pragma unroll
            for (int j = 0; j < 8; ++j) {
                ull pa = pk2(av[j]);
                ffma2(acc[j][0], pa, w1.x);
                ffma2(acc[j][1], pa, w1.y);
                ffma2(acc[j][2], pa, w2.x);
                ffma2(acc[j][3], pa, w2.y);
            }
        }
        __syncthreads();
    }

    float4 bv1 = *(const float4*)(bias + n0 + c1);
    float4 bv2 = *(const float4*)(bias + n0 + c2);
    float bvf1[4] = {bv1.x, bv1.y, bv1.z, bv1.w};
    float bvf2[4] = {bv2.x, bv2.y, bv2.z, bv2.w};
    #pragma unroll
    for (int j = 0; j < 8; ++j) {
        float o1[4], o2[4];
        {
            float2 v0 = upk(acc[j][0]), v1 = upk(acc[j][1]);
            o1[0] = v0.x + bvf1[0]; o1[1] = v0.y + bvf1[1];
            o1[2] = v1.x + bvf1[2]; o1[3] = v1.y + bvf1[3];
            float2 u0 = upk(acc[j][2]), u1 = upk(acc[j][3]);
            o2[0] = u0.x + bvf2[0]; o2[1] = u0.y + bvf2[1];
            o2[2] = u1.x + bvf2[2]; o2[3] = u1.y + bvf2[3];
        }
        if (relu) {
            #pragma unroll
            for (int c = 0; c < 4; ++c) {
                o1[c] = fmaxf(o1[c], 0.0f);
                o2[c] = fmaxf(o2[c], 0.0f);
            }
        }
        float* dst = C + (size_t)(m0 + crow + j) * N + n0;
        *(float4*)(dst + c1) = make_float4(o1[0], o1[1], o1[2], o1[3]);
        *(float4*)(dst + c2) = make_float4(o2[0], o2[1], o2[2], o2[3]);
    }
}

// ---------------------------------------------------------------------------
// Warp-MMA bf16-split GEMM with cp.async pipelined staging (unchanged, proven)
// ---------------------------------------------------------------------------
#define WMG_TILE_E  (128 * 72)
#define WMG_TILE_B  (WMG_TILE_E * 2)
#define WMG_BUF_B   (4 * WMG_TILE_B)
#define WMG_SMEM    (2 * WMG_BUF_B)

__global__ __launch_bounds__(256, 1)
void wm_gemm(const __nv_bfloat16* __restrict__ Ah, const __nv_bfloat16* __restrict__ Al,
             const __nv_bfloat16* __restrict__ Bh, const __nv_bfloat16* __restrict__ Bl,
             const float* __restrict__ bias,
             __nv_bfloat16* __restrict__ Ch, __nv_bfloat16* __restrict__ Cl,
             float* __restrict__ Cf, int Kp, int N)
{
    extern __shared__ __align__(16) __nv_bfloat16 sw[];
    const int tid  = threadIdx.x;
    const int w    = tid >> 5, lane = tid & 31;
    const int wm   = w & 3, wn = w >> 2;
    const int m0   = blockIdx.y << 7, n0 = blockIdx.x << 7;
    const int m0c  = wm * 32, n0c = wn * 64;

    float acc[2][8][4];
    #pragma unroll
    for (int mb = 0; mb < 2; ++mb)
        #pragma unroll
        for (int j = 0; j < 8; ++j)
            #pragma unroll
            for (int c = 0; c < 4; ++c) acc[mb][j][c] = 0.0f;

    const uint32_t sbase = smem_u32(sw);
    const uint32_t aByte =
        ((uint32_t)(m0c + ((lane >> 3) & 1) * 8 + (lane & 7)) * 72 + (lane >> 4) * 8) * 2;
    const uint32_t bByte =
        ((uint32_t)(n0c + (lane >> 4) * 8 + (lane & 7)) * 72 + ((lane >> 3) & 1) * 8) * 2;

    const int srow = tid >> 1;
    const int sc8  = (tid & 1) * 4;

    auto stage = [&](int t, int buf) {
        const int koff = t * 64 + sc8 * 8;
        const uint32_t dst = sbase + buf * WMG_BUF_B
                           + (uint32_t)(srow * 72 + sc8 * 8) * 2;
        const __nv_bfloat16* s0 = Ah + (size_t)(m0 + srow) * Kp + koff;
        const __nv_bfloat16* s1 = Al + (size_t)(m0 + srow) * Kp + koff;
        const __nv_bfloat16* s2 = Bh + (size_t)(n0 + srow) * Kp + koff;
        const __nv_bfloat16* s3 = Bl + (size_t)(n0 + srow) * Kp + koff;
        #pragma unroll
        for (int q = 0; q < 4; ++q) {
            cpa16(dst + q * 16,                  s0 + q * 8);
            cpa16(dst + WMG_TILE_B + q * 16,     s1 + q * 8);
            cpa16(dst + 2 * WMG_TILE_B + q * 16, s2 + q * 8);
            cpa16(dst + 3 * WMG_TILE_B + q * 16, s3 + q * 8);
        }
        CPA_COMMIT();
    };

    const int T = Kp >> 6;
    stage(0, 0);
    if (T > 1) stage(1, 1);

    for (int t = 0; t < T; ++t) {
        const int buf = t & 1;
        if (t + 1 < T) { CPA_WAIT(1); } else { CPA_WAIT(0); }
        __syncthreads();

        const uint32_t ab = sbase + buf * WMG_BUF_B;
        #pragma unroll
        for (int kk = 0; kk < 4; ++kk) {
            uint32_t a0h[4], a1h[4], a0l[4], a1l[4];
            const uint32_t ak = ab + aByte + kk * 32;
            ldm4(a0h, ak);
            ldm4(a1h, ak + 2304);
            ldm4(a0l, ak + WMG_TILE_B);
            ldm4(a1l, ak + WMG_TILE_B + 2304);
            #pragma unroll
            for (int jj = 0; jj < 4; ++jj) {
                uint32_t bh[4], bl[4];
                const uint32_t bk = ab + 2 * WMG_TILE_B + bByte + jj * 2304 + kk * 32;
                ldm4(bh, bk);
                ldm4(bl, bk + WMG_TILE_B);
                mma16816(acc[0][2*jj],     a0h, bh[0], bh[1]);
                mma16816(acc[0][2*jj],     a0h, bl[0], bl[1]);
                mma16816(acc[0][2*jj],     a0l, bh[0], bh[1]);
                mma16816(acc[0][2*jj + 1], a0h, bh[2], bh[3]);
                mma16816(acc[0][2*jj + 1], a0h, bl[2], bl[3]);
                mma16816(acc[0][2*jj + 1], a0l, bh[2], bh[3]);
                mma16816(acc[1][2*jj],     a1h, bh[0], bh[1]);
                mma16816(acc[1][2*jj],     a1h, bl[0], bl[1]);
                mma16816(acc[1][2*jj],     a1l, bh[0], bh[1]);
                mma16816(acc[1][2*jj + 1], a1h, bh[2], bh[3]);
                mma16816(acc[1][2*jj + 1], a1h, bl[2], bl[3]);
                mma16816(acc[1][2*jj + 1], a1l, bh[2], bh[3]);
            }
        }
        __syncthreads();
        if (t + 2 < T) stage(t + 2, buf);
    }

    const int lr = lane >> 2;
    const int lc = (lane & 3) * 2;
    #pragma unroll
    for (int mb = 0; mb < 2; ++mb) {
        const int r0g = m0 + m0c + 16 * mb + lr;
        const int r1g = r0g + 8;
        #pragma unroll
        for (int j = 0; j < 8; ++j) {
            const int nc = n0 + n0c + 8 * j + lc;
            float2 bv = *(const float2*)(bias + nc);
            float v00 = fmaxf(acc[mb][j][0] + bv.x, 0.0f);
            float v01 = fmaxf(acc[mb][j][1] + bv.y, 0.0f);
            float v10 = fmaxf(acc[mb][j][2] + bv.x, 0.0f);
            float v11 = fmaxf(acc[mb][j][3] + bv.y, 0.0f);
            if (Cf) {
                *(float2*)(Cf + (size_t)r0g * N + nc) = make_float2(v00, v01);
                *(float2*)(Cf + (size_t)r1g * N + nc) = make_float2(v10, v11);
            }
            if (Ch) {
                uint32_t h0, h1, l0, l1;
                asm("cvt.rn.bf16x2.f32 %0, %1, %2;" : "=r"(h0) : "f"(v01), "f"(v00));
                asm("cvt.rn.bf16x2.f32 %0, %1, %2;" : "=r"(h1) : "f"(v11), "f"(v10));
                float r00 = v00 - __uint_as_float(h0 << 16);
                float r01 = v01 - __uint_as_float(h0 & 0xffff0000u);
                float r10 = v10 - __uint_as_float(h1 << 16);
                float r11 = v11 - __uint_as_float(h1 & 0xffff0000u);
                asm("cvt.rn.bf16x2.f32 %0, %1, %2;" : "=r"(l0) : "f"(r01), "f"(r00));
                asm("cvt.rn.bf16x2.f32 %0, %1, %2;" : "=r"(l1) : "f"(r11), "f"(r10));
                *(uint32_t*)(Ch + (size_t)r0g * N + nc) = h0;
                *(uint32_t*)(Ch + (size_t)r1g * N + nc) = h1;
                *(uint32_t*)(Cl + (size_t)r0g * N + nc) = l0;
                *(uint32_t*)(Cl + (size_t)r1g * N + nc) = l1;
            }
        }
    }
}

// ---------------------------------------------------------------------------
// Head: out[b] = tanh(dot(a4[b], Wp) + bp)
// ---------------------------------------------------------------------------
__global__ void head_kernel(const float* __restrict__ A, const float* __restrict__ Wp,
                            const float* __restrict__ bp, float* __restrict__ out)
{
    __shared__ float wsh[256];
    int tid = threadIdx.x;
    wsh[tid] = Wp[tid];
    __syncthreads();
    int warp = tid >> 5, lane = tid & 31;
    int b = blockIdx.x * 8 + warp;
    const float* a = A + (size_t)b * 256;
    float s = 0.0f;
    #pragma unroll
    for (int i = 0; i < 8; ++i) s += a[lane + 32 * i] * wsh[lane + 32 * i];
    #pragma unroll
    for (int o = 16; o; o >>= 1) s += __shfl_xor_sync(0xffffffffu, s, o);
    if (lane == 0) out[b] = tanhf(s + bp[0]);
}

// ---------------------------------------------------------------------------
// Launch
// ---------------------------------------------------------------------------
extern "C" void kernel_launch(void* const* d_in, const int* in_sizes, int n_in,
                              void* d_out, int out_size)
{
    const float* state = (const float*)d_in[0];
    const float* W_ih  = (const float*)d_in[1];
    const float* W_hh  = (const float*)d_in[2];
    const float* b_ih  = (const float*)d_in[3];
    const float* b_hh  = (const float*)d_in[4];
    const float* W1 = (const float*)d_in[5];  const float* b1 = (const float*)d_in[6];
    const float* W2 = (const float*)d_in[7];  const float* b2 = (const float*)d_in[8];
    const float* W3 = (const float*)d_in[9];  const float* b3 = (const float*)d_in[10];
    const float* W4 = (const float*)d_in[11]; const float* b4 = (const float*)d_in[12];
    const float* Wp = (const float*)d_in[13]; const float* bp = (const float*)d_in[14];
    float* out = (float*)d_out;

    float *pWhhT, *pWihT, *pS16, *pXg, *pOut4;
    __nv_bfloat16 *pXh, *pXl, *pAh, *pAl, *pBh, *pBl;
    __nv_bfloat16 *pW1h, *pW1l, *pW2h, *pW2l, *pW3h, *pW3l, *pW4h, *pW4l;
    cudaGetSymbolAddress((void**)&pWhhT, g_WhhT);
    cudaGetSymbolAddress((void**)&pWihT, g_WihT);
    cudaGetSymbolAddress((void**)&pS16,  g_state16);
    cudaGetSymbolAddress((void**)&pXg,   g_xg);
    cudaGetSymbolAddress((void**)&pOut4, g_out4);
    cudaGetSymbolAddress((void**)&pXh,   g_xh);
    cudaGetSymbolAddress((void**)&pXl,   g_xl);
    cudaGetSymbolAddress((void**)&pAh,   g_ah);
    cudaGetSymbolAddress((void**)&pAl,   g_al);
    cudaGetSymbolAddress((void**)&pBh,   g_bh);
    cudaGetSymbolAddress((void**)&pBl,   g_bl);
    cudaGetSymbolAddress((void**)&pW1h,  g_w1h);
    cudaGetSymbolAddress((void**)&pW1l,  g_w1l);
    cudaGetSymbolAddress((void**)&pW2h,  g_w2h);
    cudaGetSymbolAddress((void**)&pW2l,  g_w2l);
    cudaGetSymbolAddress((void**)&pW3h,  g_w3h);
    cudaGetSymbolAddress((void**)&pW3l,  g_w3l);
    cudaGetSymbolAddress((void**)&pW4h,  g_w4h);
    cudaGetSymbolAddress((void**)&pW4l,  g_w4l);

    cudaFuncSetAttribute(gru_kernel, cudaFuncAttributeMaxDynamicSharedMemorySize,
                         GRU_SMEM_BYTES);
    cudaFuncSetAttribute(wm_gemm, cudaFuncAttributeMaxDynamicSharedMemorySize,
                         WMG_SMEM);

    // prep
    transpose_pad<<<(256 * 768 + 255) / 256, 256>>>(W_hh, pWhhT, 768, 256, 256);
    transpose_pad<<<(16 * 768 + 255) / 256, 256>>>(W_ih, pWihT, 768, 15, 16);
    pad_state16<<<(B_SZ * V_DIM * 16 + 255) / 256, 256>>>(state, pS16);
    split_w1<<<(1024 * 320 + 255) / 256, 256>>>(W1, pW1h, pW1l);
    split_pad<<<(1024 * 1024 + 255) / 256, 256>>>(W2, pW2h, pW2l, 1024, 1024, 1024);
    split_pad<<<(512 * 1024 + 255) / 256, 256>>>(W3, pW3h, pW3l, 512, 1024, 1024);
    split_pad<<<(256 * 512 + 255) / 256, 256>>>(W4, pW4h, pW4l, 256, 512, 512);

    // xg = state @ W_ih^T + b_ih  (fp32, K=16, N=768)
    mlp_gemm<<<dim3(6, 2560), 256>>>(pS16, pWihT, b_ih, pXg, 16, 768, 0);

    // GRU -> writes g_xh/g_xl [B][320] directly
    gru_kernel<<<B_SZ / 32, 512, GRU_SMEM_BYTES>>>(state, b_hh);

    // tensor-core MLP (mma.sync bf16 split, cp.async pipelined)
    wm_gemm<<<dim3(8, 128), 256, WMG_SMEM>>>(pXh, pXl, pW1h, pW1l, b1,
                                             pAh, pAl, nullptr, 320, 1024);
    wm_gemm<<<dim3(8, 128), 256, WMG_SMEM>>>(pAh, pAl, pW2h, pW2l, b2,
                                             pBh, pBl, nullptr, 1024, 1024);
    wm_gemm<<<dim3(4, 128), 256, WMG_SMEM>>>(pBh, pBl, pW3h, pW3l, b3,
                                             pAh, pAl, nullptr, 1024, 512);
    wm_gemm<<<dim3(2, 128), 256, WMG_SMEM>>>(pAh, pAl, pW4h, pW4l, b4,
                                             nullptr, nullptr, pOut4, 512, 256);

    // head
    head_kernel<<<B_SZ / 8, 256>>>(pOut4, Wp, bp, out);
}

// round 16
// speedup vs baseline: 1.6505x; 1.6505x over previous
#include <cuda_runtime.h>
#include <cuda_bf16.h>
#include <cstdint>

typedef unsigned long long ull;

#define B_SZ  16384
#define V_DIM 20
#define F_DIM 15

// ---------------------------------------------------------------------------
// f32x2 packed math helpers (fp32 GRU path)
// ---------------------------------------------------------------------------
__device__ __forceinline__ ull pk2(float a) {
    ull r; asm("mov.b64 %0, {%1, %1};" : "=l"(r) : "f"(a)); return r;
}
__device__ __forceinline__ void ffma2(ull &d, ull a, ull b) {
    asm("fma.rn.f32x2 %0, %1, %2, %0;" : "+l"(d) : "l"(a), "l"(b));
}
__device__ __forceinline__ float2 upk(ull v) {
    float2 f; asm("mov.b64 {%0, %1}, %2;" : "=f"(f.x), "=f"(f.y) : "l"(v)); return f;
}
__device__ __forceinline__ float tanhfast(float x) {
    float y; asm("tanh.approx.f32 %0, %1;" : "=f"(y) : "f"(x)); return y;
}
__device__ __forceinline__ float sigmfast(float x) {
    return fmaf(tanhfast(0.5f * x), 0.5f, 0.5f);
}

// ---------------------------------------------------------------------------
// mma.sync + cp.async helpers (sm_80+ PTX: legal on compute_103)
// ---------------------------------------------------------------------------
__device__ __forceinline__ uint32_t smem_u32(const void* p) {
    uint32_t a;
    asm("{ .reg .u64 t; cvta.to.shared.u64 t, %1; cvt.u32.u64 %0, t; }"
        : "=r"(a) : "l"(p));
    return a;
}
__device__ __forceinline__ void ldm4(uint32_t* r, uint32_t addr) {
    asm volatile("ldmatrix.sync.aligned.m8n8.x4.shared.b16 {%0,%1,%2,%3}, [%4];"
                 : "=r"(r[0]), "=r"(r[1]), "=r"(r[2]), "=r"(r[3]) : "r"(addr));
}
__device__ __forceinline__ void mma16816(float* c, const uint32_t* a,
                                         uint32_t b0, uint32_t b1) {
    asm volatile(
        "mma.sync.aligned.m16n8k16.row.col.f32.bf16.bf16.f32 "
        "{%0,%1,%2,%3}, {%4,%5,%6,%7}, {%8,%9}, {%0,%1,%2,%3};"
        : "+f"(c[0]), "+f"(c[1]), "+f"(c[2]), "+f"(c[3])
        : "r"(a[0]), "r"(a[1]), "r"(a[2]), "r"(a[3]), "r"(b0), "r"(b1));
}
__device__ __forceinline__ void cpa16(uint32_t dst, const void* src) {
    asm volatile("cp.async.cg.shared.global [%0], [%1], 16;"
                 :: "r"(dst), "l"(src));
}
#define CPA_COMMIT() asm volatile("cp.async.commit_group;" ::: "memory")
#define CPA_WAIT(n)  asm volatile("cp.async.wait_group %0;" :: "n"(n) : "memory")

// ---------------------------------------------------------------------------
// Device-global scratch
// ---------------------------------------------------------------------------
__device__ float g_Wcomb[272 * 768];     // rows 0..255 = W_hh^T, 256..271 = W_ih^T
__device__ float g_out4[(size_t)B_SZ * 256];

// bf16 split buffers (16B-aligned for uint4 / cp.async access)
__device__ __align__(16) __nv_bfloat16 g_xh[(size_t)B_SZ * 320];
__device__ __align__(16) __nv_bfloat16 g_xl[(size_t)B_SZ * 320];
__device__ __align__(16) __nv_bfloat16 g_ah[(size_t)B_SZ * 1024];
__device__ __align__(16) __nv_bfloat16 g_al[(size_t)B_SZ * 1024];
__device__ __align__(16) __nv_bfloat16 g_bh[(size_t)B_SZ * 1024];
__device__ __align__(16) __nv_bfloat16 g_bl[(size_t)B_SZ * 1024];
__device__ __align__(16) __nv_bfloat16 g_w1h[1024 * 320];
__device__ __align__(16) __nv_bfloat16 g_w1l[1024 * 320];
__device__ __align__(16) __nv_bfloat16 g_w2h[1024 * 1024];
__device__ __align__(16) __nv_bfloat16 g_w2l[1024 * 1024];
__device__ __align__(16) __nv_bfloat16 g_w3h[512 * 1024];
__device__ __align__(16) __nv_bfloat16 g_w3l[512 * 1024];
__device__ __align__(16) __nv_bfloat16 g_w4h[256 * 512];
__device__ __align__(16) __nv_bfloat16 g_w4l[256 * 512];

// ---------------------------------------------------------------------------
// Prep kernels
// ---------------------------------------------------------------------------
__global__ void transpose_pad(const float* __restrict__ in, float* __restrict__ out,
                              int N, int K, int Kp)
{
    int idx = blockIdx.x * 256 + threadIdx.x;
    if (idx >= Kp * N) return;
    int k = idx / N, n = idx - k * N;
    out[idx] = (k < K) ? in[n * K + k] : 0.0f;
}

// generic bf16 hi/lo split with K padding: in [N][K] -> out [N][Kp]
__global__ void split_pad(const float* __restrict__ in,
                          __nv_bfloat16* __restrict__ hi, __nv_bfloat16* __restrict__ lo,
                          int N, int K, int Kp)
{
    int idx = blockIdx.x * 256 + threadIdx.x;
    if (idx >= N * Kp) return;
    int n = idx / Kp, k = idx - n * Kp;
    float v = (k < K) ? in[(size_t)n * K + k] : 0.0f;
    __nv_bfloat16 h = __float2bfloat16(v);
    hi[idx] = h;
    lo[idx] = __float2bfloat16(v - __bfloat162float(h));
}

// W1 split with column permutation matching xcat = [h(256)|feat(15)|pad]
__global__ void split_w1(const float* __restrict__ W1,
                         __nv_bfloat16* __restrict__ hi, __nv_bfloat16* __restrict__ lo)
{
    int idx = blockIdx.x * 256 + threadIdx.x;
    if (idx >= 1024 * 320) return;
    int n = idx / 320, k = idx - n * 320;
    float v = 0.0f;
    if (k < 256)      v = W1[n * 271 + 15 + k];
    else if (k < 271) v = W1[n * 271 + (k - 256)];
    __nv_bfloat16 h = __float2bfloat16(v);
    hi[idx] = h;
    lo[idx] = __float2bfloat16(v - __bfloat162float(h));
}

// ---------------------------------------------------------------------------
// GRU kernel v3 (R13 shape + fused x-gates + cp.async W staging).
// CTA = 32 batch rows, 256 threads, occ 1. Thread: 8 rows x 4 cols x 3 gates
// + 4th acc group for x-side n gate. K = 272 = 256 h + 16 x (fused W_ih tile).
// h (and per-step x) transposed in SMEM [k][36-padded rows] -> broadcast loads.
// W tiles [16][768] double-buffered via cp.async, ring over 17 tiles.
// Epilogue writes bf16 hi/lo xcat directly.
// ---------------------------------------------------------------------------
#define ASTRIDE 36
#define GRU_SMEM_FLOATS (2 * 16 * 768 + 272 * ASTRIDE + 1024)
#define GRU_SMEM_BYTES  (GRU_SMEM_FLOATS * 4)

__global__ __launch_bounds__(256, 1)
void gru_kernel(const float* __restrict__ state,
                const float* __restrict__ b_ih, const float* __restrict__ b_hh)
{
    extern __shared__ __align__(16) float sm[];
    float* W_s = sm;                       // [2][16*768]
    float* A_s = sm + 2 * 16 * 768;        // [272][ASTRIDE]
    float* bi  = A_s + 272 * ASTRIDE;      // [4][256]

    const int tid  = threadIdx.x;
    const int w    = tid >> 5, lane = tid & 31;
    const int cg   = w & 1, rg = w >> 1;
    const int r0   = rg * 8;
    const int hcol = cg * 128 + lane * 4;
    const int b0   = blockIdx.x * 32;
    const uint32_t ws_u32 = smem_u32(W_s);

    for (int i = tid; i < 272 * ASTRIDE; i += 256) A_s[i] = 0.0f;
    // biases: [0]=r sum, [1]=z sum, [2]=b_hh n, [3]=b_ih n
    bi[tid]       = b_ih[tid]       + b_hh[tid];
    bi[256 + tid] = b_ih[256 + tid] + b_hh[256 + tid];
    bi[512 + tid] = b_hh[512 + tid];
    bi[768 + tid] = b_ih[512 + tid];

    // prologue: stage tile 0 via cp.async
    #pragma unroll
    for (int j = 0; j < 12; ++j) {
        int f = (tid + j * 256) * 4;
        cpa16(ws_u32 + f * 4, g_Wcomb + f);
    }
    CPA_COMMIT();
    CPA_WAIT(0);
    __syncthreads();

    ull acc[4][8][2];
    #pragma unroll
    for (int g = 0; g < 4; ++g)
        #pragma unroll
        for (int i = 0; i < 8; ++i) { acc[g][i][0] = 0ull; acc[g][i][1] = 0ull; }

    int buf = 0, nxt = 1;
    for (int t = 0; t < V_DIM; ++t) {
        // stage x features into A_s k-rows 256..270 (read at tile 16, after
        // >=1 barrier; row 271 stays zero from init)
        for (int idx = tid; idx < 32 * F_DIM; idx += 256) {
            int row = idx / F_DIM, f = idx - row * F_DIM;
            A_s[(256 + f) * ASTRIDE + row] =
                state[((size_t)(b0 + row) * V_DIM + t) * F_DIM + f];
        }

        for (int kt = 0; kt < 17; ++kt) {
            // stage next tile (ring over the 17 tiles of g_Wcomb)
            {
                const float* src = g_Wcomb + nxt * 12288;
                const uint32_t dstb = ws_u32 + (buf ^ 1) * 49152;
                #pragma unroll
                for (int j = 0; j < 12; ++j) {
                    int f = (tid + j * 256) * 4;
                    cpa16(dstb + f * 4, src + f);
                }
                CPA_COMMIT();
            }
            const float* Wb = W_s + buf * 12288;
            if (kt < 16) {
                #pragma unroll
                for (int kk = 0; kk < 16; ++kk) {
                    const int k = kt * 16 + kk;
                    float4 a0 = *(const float4*)(A_s + k * ASTRIDE + r0);
                    float4 a1 = *(const float4*)(A_s + k * ASTRIDE + r0 + 4);
                    ull pa[8];
                    pa[0] = pk2(a0.x); pa[1] = pk2(a0.y); pa[2] = pk2(a0.z); pa[3] = pk2(a0.w);
                    pa[4] = pk2(a1.x); pa[5] = pk2(a1.y); pa[6] = pk2(a1.z); pa[7] = pk2(a1.w);
                    #pragma unroll
                    for (int g = 0; g < 3; ++g) {
                        ulonglong2 wv = *(const ulonglong2*)(Wb + kk * 768 + g * 256 + hcol);
                        #pragma unroll
                        for (int i = 0; i < 8; ++i) {
                            ffma2(acc[g][i][0], pa[i], wv.x);
                            ffma2(acc[g][i][1], pa[i], wv.y);
                        }
                    }
                }
            } else {
                // x tile: k rows 256..271; n-gate goes to acc[3]
                #pragma unroll
                for (int kk = 0; kk < 16; ++kk) {
                    const int k = 256 + kk;
                    float4 a0 = *(const float4*)(A_s + k * ASTRIDE + r0);
                    float4 a1 = *(const float4*)(A_s + k * ASTRIDE + r0 + 4);
                    ull pa[8];
                    pa[0] = pk2(a0.x); pa[1] = pk2(a0.y); pa[2] = pk2(a0.z); pa[3] = pk2(a0.w);
                    pa[4] = pk2(a1.x); pa[5] = pk2(a1.y); pa[6] = pk2(a1.z); pa[7] = pk2(a1.w);
                    #pragma unroll
                    for (int g = 0; g < 3; ++g) {
                        const int ga = (g == 2) ? 3 : g;
                        ulonglong2 wv = *(const ulonglong2*)(Wb + kk * 768 + g * 256 + hcol);
                        #pragma unroll
                        for (int i = 0; i < 8; ++i) {
                            ffma2(acc[ga][i][0], pa[i], wv.x);
                            ffma2(acc[ga][i][1], pa[i], wv.y);
                        }
                    }
                }
            }
            CPA_WAIT(0);
            __syncthreads();
            buf ^= 1;
            nxt = (nxt == 16) ? 0 : nxt + 1;
        }

        // ---- epilogue: gates + state update (thread-exclusive cells) ----
        float4 bR  = *(const float4*)(bi + 0   + hcol);
        float4 bZ  = *(const float4*)(bi + 256 + hcol);
        float4 bNh = *(const float4*)(bi + 512 + hcol);
        float4 bNx = *(const float4*)(bi + 768 + hcol);
        #pragma unroll
        for (int i = 0; i < 8; ++i) {
            float2 ar0 = upk(acc[0][i][0]), ar1 = upk(acc[0][i][1]);
            float2 az0 = upk(acc[1][i][0]), az1 = upk(acc[1][i][1]);
            float2 ah0 = upk(acc[2][i][0]), ah1 = upk(acc[2][i][1]);
            float2 ax0 = upk(acc[3][i][0]), ax1 = upk(acc[3][i][1]);
            float rr[4], zz[4], nn[4];
            rr[0] = sigmfast(ar0.x + bR.x);
            rr[1] = sigmfast(ar0.y + bR.y);
            rr[2] = sigmfast(ar1.x + bR.z);
            rr[3] = sigmfast(ar1.y + bR.w);
            zz[0] = sigmfast(az0.x + bZ.x);
            zz[1] = sigmfast(az0.y + bZ.y);
            zz[2] = sigmfast(az1.x + bZ.z);
            zz[3] = sigmfast(az1.y + bZ.w);
            nn[0] = tanhfast((ax0.x + bNx.x) + rr[0] * (ah0.x + bNh.x));
            nn[1] = tanhfast((ax0.y + bNx.y) + rr[1] * (ah0.y + bNh.y));
            nn[2] = tanhfast((ax1.x + bNx.z) + rr[2] * (ah1.x + bNh.z));
            nn[3] = tanhfast((ax1.y + bNx.w) + rr[3] * (ah1.y + bNh.w));
            #pragma unroll
            for (int c = 0; c < 4; ++c) {
                float* hp = A_s + (hcol + c) * ASTRIDE + r0 + i;
                float h = *hp;
                *hp = nn[c] + zz[c] * (h - nn[c]);
            }
        }
        #pragma unroll
        for (int g = 0; g < 4; ++g)
            #pragma unroll
            for (int i = 0; i < 8; ++i) { acc[g][i][0] = 0ull; acc[g][i][1] = 0ull; }
        __syncthreads();
    }

    // ---- write xcat bf16 hi/lo directly: [h(256) | feat(15) | pad..320) ----
    #pragma unroll
    for (int i = 0; i < 8; ++i) {
        float v0 = A_s[(hcol + 0) * ASTRIDE + r0 + i];
        float v1 = A_s[(hcol + 1) * ASTRIDE + r0 + i];
        float v2 = A_s[(hcol + 2) * ASTRIDE + r0 + i];
        float v3 = A_s[(hcol + 3) * ASTRIDE + r0 + i];
        uint32_t h01, h23, l01, l23;
        asm("cvt.rn.bf16x2.f32 %0, %1, %2;" : "=r"(h01) : "f"(v1), "f"(v0));
        asm("cvt.rn.bf16x2.f32 %0, %1, %2;" : "=r"(h23) : "f"(v3), "f"(v2));
        float r0f = v0 - __uint_as_float(h01 << 16);
        float r1f = v1 - __uint_as_float(h01 & 0xffff0000u);
        float r2f = v2 - __uint_as_float(h23 << 16);
        float r3f = v3 - __uint_as_float(h23 & 0xffff0000u);
        asm("cvt.rn.bf16x2.f32 %0, %1, %2;" : "=r"(l01) : "f"(r1f), "f"(r0f));
        asm("cvt.rn.bf16x2.f32 %0, %1, %2;" : "=r"(l23) : "f"(r3f), "f"(r2f));
        size_t off = (size_t)(b0 + r0 + i) * 320 + hcol;
        *(uint2*)(g_xh + off) = make_uint2(h01, h23);
        *(uint2*)(g_xl + off) = make_uint2(l01, l23);
    }
    // features cols 256..270
    for (int idx = tid; idx < 32 * F_DIM; idx += 256) {
        int row = idx / F_DIM, f = idx - row * F_DIM;
        float v = state[((size_t)(b0 + row) * V_DIM) * F_DIM + f];
        __nv_bfloat16 h = __float2bfloat16(v);
        size_t off = (size_t)(b0 + row) * 320 + 256 + f;
        g_xh[off] = h;
        g_xl[off] = __float2bfloat16(v - __bfloat162float(h));
    }
    // zero pad cols 271..319
    for (int idx = tid; idx < 32 * 49; idx += 256) {
        int row = idx / 49, c = 271 + (idx - (idx / 49) * 49);
        size_t off = (size_t)(b0 + row) * 320 + c;
        g_xh[off] = __float2bfloat16(0.0f);
        g_xl[off] = __float2bfloat16(0.0f);
    }
}

// ---------------------------------------------------------------------------
// Warp-MMA bf16-split GEMM with cp.async pipelined staging (R13, proven)
// ---------------------------------------------------------------------------
#define WMG_TILE_E  (128 * 72)
#define WMG_TILE_B  (WMG_TILE_E * 2)
#define WMG_BUF_B   (4 * WMG_TILE_B)
#define WMG_SMEM    (2 * WMG_BUF_B)

__global__ __launch_bounds__(256, 1)
void wm_gemm(const __nv_bfloat16* __restrict__ Ah, const __nv_bfloat16* __restrict__ Al,
             const __nv_bfloat16* __restrict__ Bh, const __nv_bfloat16* __restrict__ Bl,
             const float* __restrict__ bias,
             __nv_bfloat16* __restrict__ Ch, __nv_bfloat16* __restrict__ Cl,
             float* __restrict__ Cf, int Kp, int N)
{
    extern __shared__ __align__(16) __nv_bfloat16 sw[];
    const int tid  = threadIdx.x;
    const int w    = tid >> 5, lane = tid & 31;
    const int wm   = w & 3, wn = w >> 2;
    const int m0   = blockIdx.y << 7, n0 = blockIdx.x << 7;
    const int m0c  = wm * 32, n0c = wn * 64;

    float acc[2][8][4];
    #pragma unroll
    for (int mb = 0; mb < 2; ++mb)
        #pragma unroll
        for (int j = 0; j < 8; ++j)
            #pragma unroll
            for (int c = 0; c < 4; ++c) acc[mb][j][c] = 0.0f;

    const uint32_t sbase = smem_u32(sw);
    const uint32_t aByte =
        ((uint32_t)(m0c + ((lane >> 3) & 1) * 8 + (lane & 7)) * 72 + (lane >> 4) * 8) * 2;
    const uint32_t bByte =
        ((uint32_t)(n0c + (lane >> 4) * 8 + (lane & 7)) * 72 + ((lane >> 3) & 1) * 8) * 2;

    const int srow = tid >> 1;
    const int sc8  = (tid & 1) * 4;

    auto stage = [&](int t, int buf) {
        const int koff = t * 64 + sc8 * 8;
        const uint32_t dst = sbase + buf * WMG_BUF_B
                           + (uint32_t)(srow * 72 + sc8 * 8) * 2;
        const __nv_bfloat16* s0 = Ah + (size_t)(m0 + srow) * Kp + koff;
        const __nv_bfloat16* s1 = Al + (size_t)(m0 + srow) * Kp + koff;
        const __nv_bfloat16* s2 = Bh + (size_t)(n0 + srow) * Kp + koff;
        const __nv_bfloat16* s3 = Bl + (size_t)(n0 + srow) * Kp + koff;
        #pragma unroll
        for (int q = 0; q < 4; ++q) {
            cpa16(dst + q * 16,                  s0 + q * 8);
            cpa16(dst + WMG_TILE_B + q * 16,     s1 + q * 8);
            cpa16(dst + 2 * WMG_TILE_B + q * 16, s2 + q * 8);
            cpa16(dst + 3 * WMG_TILE_B + q * 16, s3 + q * 8);
        }
        CPA_COMMIT();
    };

    const int T = Kp >> 6;
    stage(0, 0);
    if (T > 1) stage(1, 1);

    for (int t = 0; t < T; ++t) {
        const int buf = t & 1;
        if (t + 1 < T) { CPA_WAIT(1); } else { CPA_WAIT(0); }
        __syncthreads();

        const uint32_t ab = sbase + buf * WMG_BUF_B;
        #pragma unroll
        for (int kk = 0; kk < 4; ++kk) {
            uint32_t a0h[4], a1h[4], a0l[4], a1l[4];
            const uint32_t ak = ab + aByte + kk * 32;
            ldm4(a0h, ak);
            ldm4(a1h, ak + 2304);
            ldm4(a0l, ak + WMG_TILE_B);
            ldm4(a1l, ak + WMG_TILE_B + 2304);
            #pragma unroll
            for (int jj = 0; jj < 4; ++jj) {
                uint32_t bh[4], bl[4];
                const uint32_t bk = ab + 2 * WMG_TILE_B + bByte + jj * 2304 + kk * 32;
                ldm4(bh, bk);
                ldm4(bl, bk + WMG_TILE_B);
                mma16816(acc[0][2*jj],     a0h, bh[0], bh[1]);
                mma16816(acc[0][2*jj],     a0h, bl[0], bl[1]);
                mma16816(acc[0][2*jj],     a0l, bh[0], bh[1]);
                mma16816(acc[0][2*jj + 1], a0h, bh[2], bh[3]);
                mma16816(acc[0][2*jj + 1], a0h, bl[2], bl[3]);
                mma16816(acc[0][2*jj + 1], a0l, bh[2], bh[3]);
                mma16816(acc[1][2*jj],     a1h, bh[0], bh[1]);
                mma16816(acc[1][2*jj],     a1h, bl[0], bl[1]);
                mma16816(acc[1][2*jj],     a1l, bh[0], bh[1]);
                mma16816(acc[1][2*jj + 1], a1h, bh[2], bh[3]);
                mma16816(acc[1][2*jj + 1], a1h, bl[2], bl[3]);
                mma16816(acc[1][2*jj + 1], a1l, bh[2], bh[3]);
            }
        }
        __syncthreads();
        if (t + 2 < T) stage(t + 2, buf);
    }

    const int lr = lane >> 2;
    const int lc = (lane & 3) * 2;
    #pragma unroll
    for (int mb = 0; mb < 2; ++mb) {
        const int r0g = m0 + m0c + 16 * mb + lr;
        const int r1g = r0g + 8;
        #pragma unroll
        for (int j = 0; j < 8; ++j) {
            const int nc = n0 + n0c + 8 * j + lc;
            float2 bv = *(const float2*)(bias + nc);
            float v00 = fmaxf(acc[mb][j][0] + bv.x, 0.0f);
            float v01 = fmaxf(acc[mb][j][1] + bv.y, 0.0f);
            float v10 = fmaxf(acc[mb][j][2] + bv.x, 0.0f);
            float v11 = fmaxf(acc[mb][j][3] + bv.y, 0.0f);
            if (Cf) {
                *(float2*)(Cf + (size_t)r0g * N + nc) = make_float2(v00, v01);
                *(float2*)(Cf + (size_t)r1g * N + nc) = make_float2(v10, v11);
            }
            if (Ch) {
                uint32_t h0, h1, l0, l1;
                asm("cvt.rn.bf16x2.f32 %0, %1, %2;" : "=r"(h0) : "f"(v01), "f"(v00));
                asm("cvt.rn.bf16x2.f32 %0, %1, %2;" : "=r"(h1) : "f"(v11), "f"(v10));
                float r00 = v00 - __uint_as_float(h0 << 16);
                float r01 = v01 - __uint_as_float(h0 & 0xffff0000u);
                float r10 = v10 - __uint_as_float(h1 << 16);
                float r11 = v11 - __uint_as_float(h1 & 0xffff0000u);
                asm("cvt.rn.bf16x2.f32 %0, %1, %2;" : "=r"(l0) : "f"(r01), "f"(r00));
                asm("cvt.rn.bf16x2.f32 %0, %1, %2;" : "=r"(l1) : "f"(r11), "f"(r10));
                *(uint32_t*)(Ch + (size_t)r0g * N + nc) = h0;
                *(uint32_t*)(Ch + (size_t)r1g * N + nc) = h1;
                *(uint32_t*)(Cl + (size_t)r0g * N + nc) = l0;
                *(uint32_t*)(Cl + (size_t)r1g * N + nc) = l1;
            }
        }
    }
}

// ---------------------------------------------------------------------------
// Head: out[b] = tanh(dot(a4[b], Wp) + bp)
// ---------------------------------------------------------------------------
__global__ void head_kernel(const float* __restrict__ A, const float* __restrict__ Wp,
                            const float* __restrict__ bp, float* __restrict__ out)
{
    __shared__ float wsh[256];
    int tid = threadIdx.x;
    wsh[tid] = Wp[tid];
    __syncthreads();
    int warp = tid >> 5, lane = tid & 31;
    int b = blockIdx.x * 8 + warp;
    const float* a = A + (size_t)b * 256;
    float s = 0.0f;
    #pragma unroll
    for (int i = 0; i < 8; ++i) s += a[lane + 32 * i] * wsh[lane + 32 * i];
    #pragma unroll
    for (int o = 16; o; o >>= 1) s += __shfl_xor_sync(0xffffffffu, s, o);
    if (lane == 0) out[b] = tanhf(s + bp[0]);
}

// ---------------------------------------------------------------------------
// Launch
// ---------------------------------------------------------------------------
extern "C" void kernel_launch(void* const* d_in, const int* in_sizes, int n_in,
                              void* d_out, int out_size)
{
    const float* state = (const float*)d_in[0];
    const float* W_ih  = (const float*)d_in[1];
    const float* W_hh  = (const float*)d_in[2];
    const float* b_ih  = (const float*)d_in[3];
    const float* b_hh  = (const float*)d_in[4];
    const float* W1 = (const float*)d_in[5];  const float* b1 = (const float*)d_in[6];
    const float* W2 = (const float*)d_in[7];  const float* b2 = (const float*)d_in[8];
    const float* W3 = (const float*)d_in[9];  const float* b3 = (const float*)d_in[10];
    const float* W4 = (const float*)d_in[11]; const float* b4 = (const float*)d_in[12];
    const float* Wp = (const float*)d_in[13]; const float* bp = (const float*)d_in[14];
    float* out = (float*)d_out;

    float *pWcomb, *pOut4;
    __nv_bfloat16 *pXh, *pXl, *pAh, *pAl, *pBh, *pBl;
    __nv_bfloat16 *pW1h, *pW1l, *pW2h, *pW2l, *pW3h, *pW3l, *pW4h, *pW4l;
    cudaGetSymbolAddress((void**)&pWcomb, g_Wcomb);
    cudaGetSymbolAddress((void**)&pOut4, g_out4);
    cudaGetSymbolAddress((void**)&pXh,   g_xh);
    cudaGetSymbolAddress((void**)&pXl,   g_xl);
    cudaGetSymbolAddress((void**)&pAh,   g_ah);
    cudaGetSymbolAddress((void**)&pAl,   g_al);
    cudaGetSymbolAddress((void**)&pBh,   g_bh);
    cudaGetSymbolAddress((void**)&pBl,   g_bl);
    cudaGetSymbolAddress((void**)&pW1h,  g_w1h);
    cudaGetSymbolAddress((void**)&pW1l,  g_w1l);
    cudaGetSymbolAddress((void**)&pW2h,  g_w2h);
    cudaGetSymbolAddress((void**)&pW2l,  g_w2l);
    cudaGetSymbolAddress((void**)&pW3h,  g_w3h);
    cudaGetSymbolAddress((void**)&pW3l,  g_w3l);
    cudaGetSymbolAddress((void**)&pW4h,  g_w4h);
    cudaGetSymbolAddress((void**)&pW4l,  g_w4l);

    cudaFuncSetAttribute(gru_kernel, cudaFuncAttributeMaxDynamicSharedMemorySize,
                         GRU_SMEM_BYTES);
    cudaFuncSetAttribute(wm_gemm, cudaFuncAttributeMaxDynamicSharedMemorySize,
                         WMG_SMEM);

    // prep: combined GRU weights [272][768] = [WhhT | WihT(padded)]
    transpose_pad<<<(256 * 768 + 255) / 256, 256>>>(W_hh, pWcomb, 768, 256, 256);
    transpose_pad<<<(16 * 768 + 255) / 256, 256>>>(W_ih, pWcomb + 256 * 768, 768, 15, 16);
    split_w1<<<(1024 * 320 + 255) / 256, 256>>>(W1, pW1h, pW1l);
    split_pad<<<(1024 * 1024 + 255) / 256, 256>>>(W2, pW2h, pW2l, 1024, 1024, 1024);
    split_pad<<<(512 * 1024 + 255) / 256, 256>>>(W3, pW3h, pW3l, 512, 1024, 1024);
    split_pad<<<(256 * 512 + 255) / 256, 256>>>(W4, pW4h, pW4l, 256, 512, 512);

    // GRU (x-gates fused) -> writes g_xh/g_xl [B][320] directly
    gru_kernel<<<B_SZ / 32, 256, GRU_SMEM_BYTES>>>(state, b_ih, b_hh);

    // tensor-core MLP (mma.sync bf16 split, cp.async pipelined)
    wm_gemm<<<dim3(8, 128), 256, WMG_SMEM>>>(pXh, pXl, pW1h, pW1l, b1,
                                             pAh, pAl, nullptr, 320, 1024);
    wm_gemm<<<dim3(8, 128), 256, WMG_SMEM>>>(pAh, pAl, pW2h, pW2l, b2,
                                             pBh, pBl, nullptr, 1024, 1024);
    wm_gemm<<<dim3(4, 128), 256, WMG_SMEM>>>(pBh, pBl, pW3h, pW3l, b3,
                                             pAh, pAl, nullptr, 1024, 512);
    wm_gemm<<<dim3(2, 128), 256, WMG_SMEM>>>(pAh, pAl, pW4h, pW4l, b4,
                                             nullptr, nullptr, pOut4, 512, 256);

    // head
    head_kernel<<<B_SZ / 8, 256>>>(pOut4, Wp, bp, out);
}